// round 12
// baseline (speedup 1.0000x reference)
#include <cuda_runtime.h>
#include <cuda_fp16.h>
#include <cstdint>

// ============================================================================
// out[b,l,d] = sum_{i,j} x0[b,i,d]*x1[b,j,d]*filters[i*64+j, l]
// B=2048, F1=F2=64, D=16, L=16.
//
// R12: R7 topology EXACTLY (2 CTAs/SM, 8 warps, Q=w&3 mc-quarter, h=w>>2
// i-half, 4 HMMA warps/SMSP -> sustains the ~26cyc/mma cap), with the last
// 8 i's (i in [56,64)) computed in fp32 via fma.rn.f32x2 INTERLEAVED into the
// same warps' il-loop (16 j's per il, i_s = 56 + (il&7), il runs 0..31).
// Same-warp interleave avoids R11's cross-warp fma starvation of the fold.
// ============================================================================

static constexpr int NHI = 56;   // hmma i's [0,56); scalar i's [56,64)

// Pre-arranged W fragment image: [i(64)][kstep(4)][lane(32)] x 16B.
__device__ __align__(16) uint4 g_Wfrag[64 * 4 * 32];

__device__ __forceinline__ uint32_t pack_half2(float a, float b) {
    __half2 h = __floats2half2_rn(a, b);
    return *(uint32_t*)&h;
}
__device__ __forceinline__ uint32_t hmul2(uint32_t a, uint32_t b) {
    uint32_t d;
    asm("mul.rn.f16x2 %0, %1, %2;" : "=r"(d) : "r"(a), "r"(b));
    return d;
}
__device__ __forceinline__ void mma16816(float c[4], const uint4& a, const uint2& b) {
    asm volatile(
        "mma.sync.aligned.m16n8k16.row.col.f32.f16.f16.f32 "
        "{%0,%1,%2,%3}, {%4,%5,%6,%7}, {%8,%9}, {%0,%1,%2,%3};\n"
        : "+f"(c[0]), "+f"(c[1]), "+f"(c[2]), "+f"(c[3])
        : "r"(a.x), "r"(a.y), "r"(a.z), "r"(a.w), "r"(b.x), "r"(b.y));
}
__device__ __forceinline__ uint64_t dup2(float x) {
    uint64_t r;
    asm("mov.b64 %0, {%1, %1};" : "=l"(r) : "f"(x));
    return r;
}
__device__ __forceinline__ uint64_t fma2(uint64_t a, uint64_t b, uint64_t c) {
    uint64_t d;
    asm("fma.rn.f32x2 %0, %1, %2, %3;" : "=l"(d) : "l"(a), "l"(b), "l"(c));
    return d;
}

// ---------------------------------------------------------- prep kernel -----
__global__ void prep_w_kernel(const float* __restrict__ filters) {
    int idx  = blockIdx.x * 256 + threadIdx.x;    // 8192 total
    int i    = (idx >> 7) & 63;
    int t    = (idx >> 5) & 3;
    int lane = idx & 31;
    int gid = lane >> 2, q = lane & 3;
    int k0 = t * 16 + q * 2;
    int l0 = gid, l1 = gid + 8;

    float e[8];
    int ls[8] = {l0, l0, l1, l1, l0, l0, l1, l1};
    int ks[8] = {k0, k0 + 1, k0, k0 + 1, k0 + 8, k0 + 9, k0 + 8, k0 + 9};
    #pragma unroll
    for (int j = 0; j < 8; ++j)
        e[j] = filters[(i * 64 + ks[j]) * 16 + ls[j]];

    g_Wfrag[idx] = make_uint4(pack_half2(e[0], e[1]), pack_half2(e[2], e[3]),
                              pack_half2(e[4], e[5]), pack_half2(e[6], e[7]));
}

// ------------------------------------------------------------ main kernel ---
// SMEM (96KB/CTA): x0h 28K | x0f 4K | x1r 32K (persists) | ws 32K
// overlays after mainloop: wb (hmma partials 17.4K) on x0h; wb2 (9.2K) on ws.
static constexpr int SM_X0H = 0;        // 56*128 u32 fp16-dup x0 (i<56)
static constexpr int SM_X0F = 28672;    // 8*128 f32 x0 (i>=56)
static constexpr int SM_X1R = 32768;    // 8192 f32 raw x1 [bl][j][d]
static constexpr int SM_WS  = 65536;    // 8*64*16 f32 filters slice (i>=56)
static constexpr int SM_WB  = SM_X0H;
static constexpr int SM_WB2 = SM_WS;    // 128 m * 18 pad
static constexpr int SMEM_TOTAL = 98304;

__global__ __launch_bounds__(256, 2) void fm_main_kernel(
    const float* __restrict__ x0g,
    const float* __restrict__ x1g,
    const float* __restrict__ filters,
    float* __restrict__ outg)
{
    extern __shared__ __align__(16) unsigned char smem[];
    uint32_t* x0h = (uint32_t*)(smem + SM_X0H);
    float*    x0f = (float*)(smem + SM_X0F);
    float*    x1r = (float*)(smem + SM_X1R);
    float*    ws  = (float*)(smem + SM_WS);
    float*    wb  = (float*)(smem + SM_WB);
    float*    wb2 = (float*)(smem + SM_WB2);

    int tid = threadIdx.x;
    int w = tid >> 5, lane = tid & 31;
    int gid = lane >> 2, q = lane & 3;
    int Q = w & 3;          // mc-quarter (hmma role)
    int h = w >> 2;         // i-half of [0,56) (hmma role); also l-half (scalar)
    int bbase = blockIdx.x * 8;   // 8 b's -> 128 m rows per CTA

    // ---- stage x1 (persistent), ws (filters slice), x0h/x0f ----
    {
        const float4* src = (const float4*)(x1g + (size_t)bbase * 1024);
        float4* dst = (float4*)x1r;
        for (int e = tid; e < 2048; e += 256) dst[e] = src[e];
        const float4* fsrc = (const float4*)(filters + NHI * 1024);
        float4* wsd = (float4*)ws;
        for (int e = tid; e < 2048; e += 256) wsd[e] = fsrc[e];
        const float* x0p = x0g + (size_t)bbase * 1024;
        for (int e = tid; e < 8192; e += 256) {
            int i = e >> 7, m = e & 127;
            float v = x0p[(m >> 4) * 1024 + i * 16 + (m & 15)];
            if (i < NHI) {
                __half hh = __float2half(v);
                x0h[i * 128 + m] = (uint32_t)(*(unsigned short*)&hh) * 0x00010001u;
            } else {
                x0f[(i - NHI) * 128 + m] = v;
            }
        }
    }
    __syncthreads();

    // ---- register B fragments from x1r (R7 scheme) ----
    uint2 Bf[4][4];
    #pragma unroll
    for (int mcl = 0; mcl < 4; ++mcl) {
        int r = (Q * 4 + mcl) * 8 + gid;
        const float* base = x1r + (r >> 4) * 1024 + (r & 15);
        #pragma unroll
        for (int t = 0; t < 4; ++t) {
            int k0 = t * 16 + q * 2;
            Bf[mcl][t] = make_uint2(
                pack_half2(base[k0 * 16], base[(k0 + 1) * 16]),
                pack_half2(base[(k0 + 8) * 16], base[(k0 + 9) * 16]));
        }
    }

    // ---- accumulators ----
    float acc[4][4];
    #pragma unroll
    for (int mcl = 0; mcl < 4; ++mcl)
        #pragma unroll
        for (int r = 0; r < 4; ++r) acc[mcl][r] = 0.0f;
    uint64_t a2[4] = {0ull, 0ull, 0ull, 0ull};   // scalar: 1 m x 8 l (l-half h)

    int sm_ = Q * 32 + lane;                      // scalar m for this thread
    int sboff = (sm_ >> 4) * 1024 + (sm_ & 15);   // x1r base for scalar m

    const uint4* wp = g_Wfrag + lane;
    int i0 = h * 28;
    uint4 Wc[4], Wn[4];
    #pragma unroll
    for (int t = 0; t < 4; ++t) Wc[t] = wp[(i0 * 4 + t) * 32];

    // ---- mainloop: 32 il; hmma active il<28; scalar chunk every il ----
    for (int il = 0; il < 32; ++il) {
        if (il < 27) {
            #pragma unroll
            for (int t = 0; t < 4; ++t) Wn[t] = wp[((i0 + il + 1) * 4 + t) * 32];
        }
        if (il < 28) {
            int i = i0 + il;
            const uint32_t* x0row = x0h + i * 128;
            #pragma unroll
            for (int mcl = 0; mcl < 4; ++mcl) {
                uint32_t xh = x0row[(Q * 4 + mcl) * 8 + gid];
                #pragma unroll
                for (int t = 0; t < 4; ++t) {
                    uint2 bs = make_uint2(hmul2(Bf[mcl][t].x, xh),
                                          hmul2(Bf[mcl][t].y, xh));
                    mma16816(acc[mcl], Wc[t], bs);
                }
            }
            #pragma unroll
            for (int t = 0; t < 4; ++t) Wc[t] = Wn[t];
        }
        // scalar chunk: i_s = 56 + (il&7), j in [ (il>>3)*16, +16 )
        {
            int isl = il & 7;
            int jb = (il >> 3) * 16;
            float x0c = x0f[isl * 128 + sm_];
            const float* wrow = ws + isl * 1024 + jb * 16 + h * 8;
            const float* x1b = x1r + sboff + jb * 16;
            #pragma unroll
            for (int jj = 0; jj < 16; ++jj) {
                uint64_t pd = dup2(x0c * x1b[jj * 16]);
                ulonglong2 w0 = *(const ulonglong2*)(wrow + jj * 16);
                ulonglong2 w1 = *(const ulonglong2*)(wrow + jj * 16 + 4);
                a2[0] = fma2(w0.x, pd, a2[0]);
                a2[1] = fma2(w0.y, pd, a2[1]);
                a2[2] = fma2(w1.x, pd, a2[2]);
                a2[3] = fma2(w1.y, pd, a2[3]);
            }
        }
    }

    __syncthreads();   // all mainloop SMEM reads done; overlays safe

    // ---- hmma partial writeback (R7 scheme, pad 136) ----
    #pragma unroll
    for (int mcl = 0; mcl < 4; ++mcl) {
        float* bptr = wb + (w * 4 + mcl) * 136;
        *(float2*)&bptr[gid * 8 + 2 * q]       = make_float2(acc[mcl][0], acc[mcl][1]);
        *(float2*)&bptr[(gid + 8) * 8 + 2 * q] = make_float2(acc[mcl][2], acc[mcl][3]);
    }
    // ---- scalar partial writeback: wb2[m*18 + h*8 + l'] (pad 18) ----
    {
        float* dst = wb2 + sm_ * 18 + h * 8;
        *(uint64_t*)&dst[0] = a2[0];
        *(uint64_t*)&dst[2] = a2[1];
        *(uint64_t*)&dst[4] = a2[2];
        *(uint64_t*)&dst[6] = a2[3];
    }
    __syncthreads();

    // ---- final reduce: 2 hmma h-halves + scalar; coalesced store ----
    for (int o = tid; o < 2048; o += 256) {
        int l = o >> 7, m = o & 127;
        int Q2 = m >> 5, mcl = (m >> 3) & 3, mloc = m & 7;
        int off = (Q2 * 4 + mcl) * 136 + l * 8 + mloc;
        float s = wb[off] + wb[off + 16 * 136] + wb2[m * 18 + l];
        int bl = m >> 4, d = m & 15;
        outg[(size_t)(bbase + bl) * 256 + l * 16 + d] = s;
    }
}

// ------------------------------------------------------------------ launch --
extern "C" void kernel_launch(void* const* d_in, const int* in_sizes, int n_in,
                              void* d_out, int out_size) {
    const float* x0 = (const float*)d_in[0];
    const float* x1 = (const float*)d_in[1];
    const float* filters = (const float*)d_in[2];
    float* out = (float*)d_out;

    cudaFuncSetAttribute(fm_main_kernel,
                         cudaFuncAttributeMaxDynamicSharedMemorySize, SMEM_TOTAL);

    prep_w_kernel<<<32, 256>>>(filters);
    fm_main_kernel<<<256, 256, SMEM_TOTAL>>>(x0, x1, filters, out);
}

// round 14
// speedup vs baseline: 1.9468x; 1.9468x over previous
#include <cuda_runtime.h>
#include <cuda_fp16.h>
#include <cstdint>

// ============================================================================
// out[b,l,d] = sum_{i,j} x0[b,i,d]*x1[b,j,d]*filters[i*64+j, l]
// B=2048, F1=F2=64, D=16, L=16.
//
// R13 (resubmit; infra flake last round): pure-HMMA, wave-balanced.
// Dual-pipe falsified (R9-R12: scalar work starves the in-order mma issue
// stream). R7's critical path = imbalanced 2048 mma/SMSP; chip average 1771.
// Fix: grid=148 (1 CTA/SM), CTA=13-14 b, uniform 1792 mma/SMSP on every SM
// (clamped garbage chunks for nb=13). 8 warps (2/SMSP, sufficient per R4),
// warp = (Q = w&3 -> 7 mc, h = w>>2 -> 32 i). x0 folded via hmul2 (R7).
// ============================================================================

static constexpr int MMAX = 224;  // max m rows per CTA (14 b)

// Pre-arranged W fragment image: [i(64)][kstep(4)][lane(32)] x 16B.
__device__ __align__(16) uint4 g_Wfrag[64 * 4 * 32];

__device__ __forceinline__ uint32_t pack_half2(float a, float b) {
    __half2 h = __floats2half2_rn(a, b);
    return *(uint32_t*)&h;
}
__device__ __forceinline__ uint32_t hmul2(uint32_t a, uint32_t b) {
    uint32_t d;
    asm("mul.rn.f16x2 %0, %1, %2;" : "=r"(d) : "r"(a), "r"(b));
    return d;
}
__device__ __forceinline__ void mma16816(float c[4], const uint4& a, const uint2& b) {
    asm volatile(
        "mma.sync.aligned.m16n8k16.row.col.f32.f16.f16.f32 "
        "{%0,%1,%2,%3}, {%4,%5,%6,%7}, {%8,%9}, {%0,%1,%2,%3};\n"
        : "+f"(c[0]), "+f"(c[1]), "+f"(c[2]), "+f"(c[3])
        : "r"(a.x), "r"(a.y), "r"(a.z), "r"(a.w), "r"(b.x), "r"(b.y));
}

// ---------------------------------------------------------- prep kernel -----
// A-fragment mapping (m16k16, row-major), lane = 4*gid + q:
//   reg0 = {A[gid][2q],   A[gid][2q+1]}    reg1 = {A[gid+8][2q],   A[gid+8][2q+1]}
//   reg2 = {A[gid][2q+8], A[gid][2q+9]}    reg3 = {A[gid+8][2q+8], A[gid+8][2q+9]}
__global__ void prep_w_kernel(const float* __restrict__ filters) {
    int idx  = blockIdx.x * 256 + threadIdx.x;    // 8192 total
    int i    = (idx >> 7) & 63;
    int t    = (idx >> 5) & 3;
    int lane = idx & 31;
    int gid = lane >> 2, q = lane & 3;
    int k0 = t * 16 + q * 2;
    int l0 = gid, l1 = gid + 8;

    float e[8];
    int ls[8] = {l0, l0, l1, l1, l0, l0, l1, l1};
    int ks[8] = {k0, k0 + 1, k0, k0 + 1, k0 + 8, k0 + 9, k0 + 8, k0 + 9};
    #pragma unroll
    for (int j = 0; j < 8; ++j)
        e[j] = filters[(i * 64 + ks[j]) * 16 + ls[j]];

    g_Wfrag[idx] = make_uint4(pack_half2(e[0], e[1]), pack_half2(e[2], e[3]),
                              pack_half2(e[4], e[5]), pack_half2(e[6], e[7]));
}

// ------------------------------------------------------------ main kernel ---
// SMEM: x0h 64*224 u32 (57344) | x1r 14*1024 f32 (57344)  -> 114688 total
// overlay after mainloop: wb (56 bufs * 136 f = 30464) on x0h.
static constexpr int SM_X0H = 0;
static constexpr int SM_X1R = 57344;
static constexpr int SM_WB  = SM_X0H;
static constexpr int SMEM_TOTAL = 114688;

__global__ __launch_bounds__(256, 1) void fm_main_kernel(
    const float* __restrict__ x0g,
    const float* __restrict__ x1g,
    float* __restrict__ outg)
{
    extern __shared__ __align__(16) unsigned char smem[];
    uint32_t* x0h = (uint32_t*)(smem + SM_X0H);
    float*    x1r = (float*)(smem + SM_X1R);
    float*    wb  = (float*)(smem + SM_WB);

    int tid = threadIdx.x;
    int w = tid >> 5, lane = tid & 31;
    int gid = lane >> 2, q = lane & 3;
    int bid = blockIdx.x;
    int nb    = (bid < 124) ? 14 : 13;
    int bbase = (bid < 124) ? bid * 14 : 1736 + (bid - 124) * 13;
    int mcmax = 2 * nb - 1;

    // ---- stage x1 raw + x0 (fp16-dup, all 64 i) ----
    {
        const float4* src = (const float4*)(x1g + (size_t)bbase * 1024);
        float4* dst = (float4*)x1r;
        for (int e = tid; e < nb * 256; e += 256) dst[e] = src[e];
        const float* x0p = x0g + (size_t)bbase * 1024;
        for (int e = tid; e < nb * 1024; e += 256) {
            int bl = e >> 10, r = e & 1023;
            int i = r >> 4, d = r & 15;
            float v = x0p[e];
            __half hh = __float2half(v);
            x0h[i * MMAX + bl * 16 + d] =
                (uint32_t)(*(unsigned short*)&hh) * 0x00010001u;
        }
    }
    __syncthreads();

    // ---- warp roles: Q = w&3 (7 mc chunks), h = w>>2 (32 i's) ----
    int Q = w & 3, h = w >> 2;

    int moff[7];
    #pragma unroll
    for (int mcl = 0; mcl < 7; ++mcl) {
        int mc = Q * 7 + mcl;
        if (mc > mcmax) mc = mcmax;   // nb=13: duplicate garbage, discarded
        moff[mcl] = mc * 8 + gid;
    }

    // register B fragments from x1r
    uint2 Bf[7][4];
    #pragma unroll
    for (int mcl = 0; mcl < 7; ++mcl) {
        int r = moff[mcl];
        const float* base = x1r + (r >> 4) * 1024 + (r & 15);
        #pragma unroll
        for (int t = 0; t < 4; ++t) {
            int k0 = t * 16 + q * 2;
            Bf[mcl][t] = make_uint2(
                pack_half2(base[k0 * 16], base[(k0 + 1) * 16]),
                pack_half2(base[(k0 + 8) * 16], base[(k0 + 9) * 16]));
        }
    }

    float acc[7][4];
    #pragma unroll
    for (int mcl = 0; mcl < 7; ++mcl)
        #pragma unroll
        for (int r = 0; r < 4; ++r) acc[mcl][r] = 0.0f;

    const uint4* wp = g_Wfrag + lane;
    int i0 = h * 32;
    uint4 Wc[4], Wn[4];
    #pragma unroll
    for (int t = 0; t < 4; ++t) Wc[t] = wp[(i0 * 4 + t) * 32];

    // ---- mainloop: 32 i's, 7 mc each, 4 ksteps -> 896 mma per warp ----
    for (int il = 0; il < 32; ++il) {
        int i = i0 + il;
        if (il < 31) {
            #pragma unroll
            for (int t = 0; t < 4; ++t) Wn[t] = wp[((i + 1) * 4 + t) * 32];
        }
        const uint32_t* x0row = x0h + i * MMAX;
        #pragma unroll
        for (int mcl = 0; mcl < 7; ++mcl) {
            uint32_t xh = x0row[moff[mcl]];
            #pragma unroll
            for (int t = 0; t < 4; ++t) {
                uint2 bs = make_uint2(hmul2(Bf[mcl][t].x, xh),
                                      hmul2(Bf[mcl][t].y, xh));
                mma16816(acc[mcl], Wc[t], bs);
            }
        }
        #pragma unroll
        for (int t = 0; t < 4; ++t) Wc[t] = Wn[t];
    }

    __syncthreads();   // all x0h/x1r reads done; wb overlay safe

    // ---- partial writeback: wb[(w*7+mcl)*136 + l*8 + m_in_chunk] ----
    #pragma unroll
    for (int mcl = 0; mcl < 7; ++mcl) {
        float* bptr = wb + (w * 7 + mcl) * 136;
        *(float2*)&bptr[gid * 8 + 2 * q]       = make_float2(acc[mcl][0], acc[mcl][1]);
        *(float2*)&bptr[(gid + 8) * 8 + 2 * q] = make_float2(acc[mcl][2], acc[mcl][3]);
    }
    __syncthreads();

    // ---- final reduce: 2 i-halves; coalesced store ----
    for (int o = tid; o < nb * 256; o += 256) {
        int bl = o >> 8, l = (o >> 4) & 15, d = o & 15;
        int m = bl * 16 + d;
        int mc = m >> 3;
        int Q2 = (mc * 9363) >> 16;    // mc / 7 for mc < 28
        int mcl = mc - Q2 * 7;
        int e = mcl * 136 + l * 8 + (m & 7);
        float s = wb[(Q2 * 7) * 136 + e] + wb[((4 + Q2) * 7) * 136 + e];
        outg[(size_t)(bbase + bl) * 256 + l * 16 + d] = s;
    }
}

// ------------------------------------------------------------------ launch --
extern "C" void kernel_launch(void* const* d_in, const int* in_sizes, int n_in,
                              void* d_out, int out_size) {
    const float* x0 = (const float*)d_in[0];
    const float* x1 = (const float*)d_in[1];
    const float* filters = (const float*)d_in[2];
    float* out = (float*)d_out;

    cudaFuncSetAttribute(fm_main_kernel,
                         cudaFuncAttributeMaxDynamicSharedMemorySize, SMEM_TOTAL);

    prep_w_kernel<<<32, 256>>>(filters);
    fm_main_kernel<<<148, 256, SMEM_TOTAL>>>(x0, x1, out);
}

// round 15
// speedup vs baseline: 1.9794x; 1.0168x over previous
#include <cuda_runtime.h>
#include <cuda_fp16.h>
#include <cstdint>

// ============================================================================
// out[b,l,d] = sum_{i,j} x0[b,i,d]*x1[b,j,d]*filters[i*64+j, l]
// B=2048, F1=F2=64, D=16, L=16.
//
// R15: R14 (wave-balanced pure-HMMA, best 25.2us) + prologue trimming:
//  - x0 staging vectorized (float4 LDG -> uint4 STS, 4x fewer instrs)
//  - B-fragments built cooperatively into SMEM in lane order (conflict-free),
//    warps then load Bf via LDS.64 instead of 112 strided LDS.32 each.
// Mainloop / clamping / writeback identical to R14.
// ============================================================================

static constexpr int MMAX = 224;  // max m rows per CTA (14 b)

// Pre-arranged W fragment image: [i(64)][kstep(4)][lane(32)] x 16B.
__device__ __align__(16) uint4 g_Wfrag[64 * 4 * 32];

__device__ __forceinline__ uint32_t pack_half2(float a, float b) {
    __half2 h = __floats2half2_rn(a, b);
    return *(uint32_t*)&h;
}
__device__ __forceinline__ uint32_t hmul2(uint32_t a, uint32_t b) {
    uint32_t d;
    asm("mul.rn.f16x2 %0, %1, %2;" : "=r"(d) : "r"(a), "r"(b));
    return d;
}
__device__ __forceinline__ void mma16816(float c[4], const uint4& a, const uint2& b) {
    asm volatile(
        "mma.sync.aligned.m16n8k16.row.col.f32.f16.f16.f32 "
        "{%0,%1,%2,%3}, {%4,%5,%6,%7}, {%8,%9}, {%0,%1,%2,%3};\n"
        : "+f"(c[0]), "+f"(c[1]), "+f"(c[2]), "+f"(c[3])
        : "r"(a.x), "r"(a.y), "r"(a.z), "r"(a.w), "r"(b.x), "r"(b.y));
}

// ---------------------------------------------------------- prep kernel -----
// A-fragment mapping (m16k16, row-major), lane = 4*gid + q:
//   reg0 = {A[gid][2q],   A[gid][2q+1]}    reg1 = {A[gid+8][2q],   A[gid+8][2q+1]}
//   reg2 = {A[gid][2q+8], A[gid][2q+9]}    reg3 = {A[gid+8][2q+8], A[gid+8][2q+9]}
__global__ void prep_w_kernel(const float* __restrict__ filters) {
    int idx  = blockIdx.x * 256 + threadIdx.x;    // 8192 total
    int i    = (idx >> 7) & 63;
    int t    = (idx >> 5) & 3;
    int lane = idx & 31;
    int gid = lane >> 2, q = lane & 3;
    int k0 = t * 16 + q * 2;
    int l0 = gid, l1 = gid + 8;

    float e[8];
    int ls[8] = {l0, l0, l1, l1, l0, l0, l1, l1};
    int ks[8] = {k0, k0 + 1, k0, k0 + 1, k0 + 8, k0 + 9, k0 + 8, k0 + 9};
    #pragma unroll
    for (int j = 0; j < 8; ++j)
        e[j] = filters[(i * 64 + ks[j]) * 16 + ls[j]];

    g_Wfrag[idx] = make_uint4(pack_half2(e[0], e[1]), pack_half2(e[2], e[3]),
                              pack_half2(e[4], e[5]), pack_half2(e[6], e[7]));
}

// ------------------------------------------------------------ main kernel ---
// SMEM: x0h 64*224 u32 (57344) | x1r 14*1024 f32 (57344) | fB 3584 uint2 (28672)
//   total 143360.  Overlay after mainloop: wb (56 bufs * 136 f) on x0h.
static constexpr int SM_X0H = 0;
static constexpr int SM_X1R = 57344;
static constexpr int SM_FB  = 114688;
static constexpr int SM_WB  = SM_X0H;
static constexpr int SMEM_TOTAL = 143360;

__global__ __launch_bounds__(256, 1) void fm_main_kernel(
    const float* __restrict__ x0g,
    const float* __restrict__ x1g,
    float* __restrict__ outg)
{
    extern __shared__ __align__(16) unsigned char smem[];
    uint32_t* x0h = (uint32_t*)(smem + SM_X0H);
    float*    x1r = (float*)(smem + SM_X1R);
    uint2*    fB  = (uint2*)(smem + SM_FB);
    float*    wb  = (float*)(smem + SM_WB);

    int tid = threadIdx.x;
    int w = tid >> 5, lane = tid & 31;
    int gid = lane >> 2, q = lane & 3;
    int bid = blockIdx.x;
    int nb    = (bid < 124) ? 14 : 13;
    int bbase = (bid < 124) ? bid * 14 : 1736 + (bid - 124) * 13;
    int mcmax = 2 * nb - 1;

    // ---- stage x1 raw (float4) + x0 (float4 -> fp16-dup uint4) ----
    {
        const float4* src = (const float4*)(x1g + (size_t)bbase * 1024);
        float4* dst = (float4*)x1r;
        for (int e = tid; e < nb * 256; e += 256) dst[e] = src[e];
        const float4* x0s = (const float4*)(x0g + (size_t)bbase * 1024);
        for (int e = tid; e < nb * 256; e += 256) {
            int bl = e >> 8, r = e & 255;
            int i = r >> 2, dq = r & 3;
            float4 v = x0s[e];
            __half h0 = __float2half(v.x), h1 = __float2half(v.y);
            __half h2 = __float2half(v.z), h3 = __float2half(v.w);
            uint4 pk = make_uint4(
                (uint32_t)(*(unsigned short*)&h0) * 0x00010001u,
                (uint32_t)(*(unsigned short*)&h1) * 0x00010001u,
                (uint32_t)(*(unsigned short*)&h2) * 0x00010001u,
                (uint32_t)(*(unsigned short*)&h3) * 0x00010001u);
            *(uint4*)&x0h[i * MMAX + bl * 16 + dq * 4] = pk;
        }
    }
    __syncthreads();

    // ---- build B fragments cooperatively: fB[mc*128 + t*32 + ln] ----
    // entry = {x1[r][k0],[k0+1]} , {[k0+8],[k0+9]} with r = mc*8+(ln>>2),
    // k0 = t*16 + (ln&3)*2.  3584 entries, 14 iter/thread, conflict-light.
    for (int e = tid; e < 3584; e += 256) {
        int mc = e >> 7, t = (e >> 5) & 3, ln = e & 31;
        int r = mc * 8 + (ln >> 2);
        int k0 = t * 16 + (ln & 3) * 2;
        const float* base = x1r + (r >> 4) * 1024 + (r & 15);
        fB[e] = make_uint2(
            pack_half2(base[k0 * 16], base[(k0 + 1) * 16]),
            pack_half2(base[(k0 + 8) * 16], base[(k0 + 9) * 16]));
    }
    __syncthreads();

    // ---- warp roles: Q = w&3 (7 mc chunks), h = w>>2 (32 i's) ----
    int Q = w & 3, h = w >> 2;

    int moff[7];
    int mcc[7];
    #pragma unroll
    for (int mcl = 0; mcl < 7; ++mcl) {
        int mc = Q * 7 + mcl;
        if (mc > mcmax) mc = mcmax;   // nb=13: duplicate garbage, discarded
        mcc[mcl] = mc;
        moff[mcl] = mc * 8 + gid;
    }

    // register B fragments via clean LDS.64
    uint2 Bf[7][4];
    #pragma unroll
    for (int mcl = 0; mcl < 7; ++mcl) {
        const uint2* fp = fB + mcc[mcl] * 128 + lane;
        #pragma unroll
        for (int t = 0; t < 4; ++t)
            Bf[mcl][t] = fp[t * 32];
    }

    float acc[7][4];
    #pragma unroll
    for (int mcl = 0; mcl < 7; ++mcl)
        #pragma unroll
        for (int r = 0; r < 4; ++r) acc[mcl][r] = 0.0f;

    const uint4* wp = g_Wfrag + lane;
    int i0 = h * 32;
    uint4 Wc[4], Wn[4];
    #pragma unroll
    for (int t = 0; t < 4; ++t) Wc[t] = wp[(i0 * 4 + t) * 32];

    // ---- mainloop: 32 i's, 7 mc each, 4 ksteps -> 896 mma per warp ----
    for (int il = 0; il < 32; ++il) {
        int i = i0 + il;
        if (il < 31) {
            #pragma unroll
            for (int t = 0; t < 4; ++t) Wn[t] = wp[((i + 1) * 4 + t) * 32];
        }
        const uint32_t* x0row = x0h + i * MMAX;
        #pragma unroll
        for (int mcl = 0; mcl < 7; ++mcl) {
            uint32_t xh = x0row[moff[mcl]];
            #pragma unroll
            for (int t = 0; t < 4; ++t) {
                uint2 bs = make_uint2(hmul2(Bf[mcl][t].x, xh),
                                      hmul2(Bf[mcl][t].y, xh));
                mma16816(acc[mcl], Wc[t], bs);
            }
        }
        #pragma unroll
        for (int t = 0; t < 4; ++t) Wc[t] = Wn[t];
    }

    __syncthreads();   // all x0h/x1r/fB reads done; wb overlay safe

    // ---- partial writeback: wb[(w*7+mcl)*136 + l*8 + m_in_chunk] ----
    #pragma unroll
    for (int mcl = 0; mcl < 7; ++mcl) {
        float* bptr = wb + (w * 7 + mcl) * 136;
        *(float2*)&bptr[gid * 8 + 2 * q]       = make_float2(acc[mcl][0], acc[mcl][1]);
        *(float2*)&bptr[(gid + 8) * 8 + 2 * q] = make_float2(acc[mcl][2], acc[mcl][3]);
    }
    __syncthreads();

    // ---- final reduce: 2 i-halves; coalesced store ----
    for (int o = tid; o < nb * 256; o += 256) {
        int bl = o >> 8, l = (o >> 4) & 15, d = o & 15;
        int m = bl * 16 + d;
        int mc = m >> 3;
        int Q2 = (mc * 9363) >> 16;    // mc / 7 for mc < 28
        int mcl = mc - Q2 * 7;
        int e = mcl * 136 + l * 8 + (m & 7);
        float s = wb[(Q2 * 7) * 136 + e] + wb[((4 + Q2) * 7) * 136 + e];
        outg[(size_t)(bbase + bl) * 256 + l * 16 + d] = s;
    }
}

// ------------------------------------------------------------------ launch --
extern "C" void kernel_launch(void* const* d_in, const int* in_sizes, int n_in,
                              void* d_out, int out_size) {
    const float* x0 = (const float*)d_in[0];
    const float* x1 = (const float*)d_in[1];
    const float* filters = (const float*)d_in[2];
    float* out = (float*)d_out;

    cudaFuncSetAttribute(fm_main_kernel,
                         cudaFuncAttributeMaxDynamicSharedMemorySize, SMEM_TOTAL);

    prep_w_kernel<<<32, 256>>>(filters);
    fm_main_kernel<<<148, 256, SMEM_TOTAL>>>(x0, x1, out);
}

// round 16
// speedup vs baseline: 2.1818x; 1.1023x over previous
#include <cuda_runtime.h>
#include <cuda_fp16.h>
#include <cstdint>

// ============================================================================
// out[b,l,d] = sum_{i,j} x0[b,i,d]*x1[b,j,d]*filters[i*64+j, l]
// B=2048, F1=F2=64, D=16, L=16.
//
// R16: R15 (wave-balanced, grid=148, nb 13/14, clamped chunks) with the
// mainloop dependency structure of R4: pure-fp16 B fragments (NO hmul2 in
// the mma operand path), fresh 4-deep mma chain per (mcl, il), x0 contracted
// in fp32 FFMA on the mma OUTPUTS. Cross-round rates: operand-path fold =
// 28.5 cyc/mma/SMSP (R7/R13/R15); output-path fold = 22.5 (R4). Also
// restores x0 to fp32 (removes its fp16 rounding -> rel_err ~2.9e-4).
// ============================================================================

static constexpr int MMAX = 224;  // max m rows per CTA (14 b)

// Pre-arranged W fragment image: [i(64)][kstep(4)][lane(32)] x 16B.
__device__ __align__(16) uint4 g_Wfrag[64 * 4 * 32];

__device__ __forceinline__ uint32_t pack_half2(float a, float b) {
    __half2 h = __floats2half2_rn(a, b);   // .x (low 16b) = a, .y = b
    return *(uint32_t*)&h;
}
__device__ __forceinline__ void mma16816(float c[4], const uint4& a, const uint2& b) {
    asm volatile(
        "mma.sync.aligned.m16n8k16.row.col.f32.f16.f16.f32 "
        "{%0,%1,%2,%3}, {%4,%5,%6,%7}, {%8,%9}, {%0,%1,%2,%3};\n"
        : "+f"(c[0]), "+f"(c[1]), "+f"(c[2]), "+f"(c[3])
        : "r"(a.x), "r"(a.y), "r"(a.z), "r"(a.w), "r"(b.x), "r"(b.y));
}

// ---------------------------------------------------------- prep kernel -----
// A-fragment mapping (m16k16, row-major), lane = 4*gid + q:
//   reg0 = {A[gid][2q],   A[gid][2q+1]}    reg1 = {A[gid+8][2q],   A[gid+8][2q+1]}
//   reg2 = {A[gid][2q+8], A[gid][2q+9]}    reg3 = {A[gid+8][2q+8], A[gid+8][2q+9]}
__global__ void prep_w_kernel(const float* __restrict__ filters) {
    int idx  = blockIdx.x * 256 + threadIdx.x;    // 8192 total
    int i    = (idx >> 7) & 63;
    int t    = (idx >> 5) & 3;
    int lane = idx & 31;
    int gid = lane >> 2, q = lane & 3;
    int k0 = t * 16 + q * 2;
    int l0 = gid, l1 = gid + 8;

    float e[8];
    int ls[8] = {l0, l0, l1, l1, l0, l0, l1, l1};
    int ks[8] = {k0, k0 + 1, k0, k0 + 1, k0 + 8, k0 + 9, k0 + 8, k0 + 9};
    #pragma unroll
    for (int j = 0; j < 8; ++j)
        e[j] = filters[(i * 64 + ks[j]) * 16 + ls[j]];

    g_Wfrag[idx] = make_uint4(pack_half2(e[0], e[1]), pack_half2(e[2], e[3]),
                              pack_half2(e[4], e[5]), pack_half2(e[6], e[7]));
}

// ------------------------------------------------------------ main kernel ---
// SMEM: x0p 64*112 float2 (57344) | x1r 14*1024 f32 (57344) | fB 3584 uint2
//   (28672) -> 143360.  Overlay after mainloop: wb (56 bufs * 136 f) on x0p.
static constexpr int SM_X0P = 0;
static constexpr int SM_X1R = 57344;
static constexpr int SM_FB  = 114688;
static constexpr int SM_WB  = SM_X0P;
static constexpr int SMEM_TOTAL = 143360;

__global__ __launch_bounds__(256, 1) void fm_main_kernel(
    const float* __restrict__ x0g,
    const float* __restrict__ x1g,
    float* __restrict__ outg)
{
    extern __shared__ __align__(16) unsigned char smem[];
    float2*   x0p = (float2*)(smem + SM_X0P);   // [i][m/2] fp32 pairs
    float*    x1r = (float*)(smem + SM_X1R);
    uint2*    fB  = (uint2*)(smem + SM_FB);
    float*    wb  = (float*)(smem + SM_WB);

    int tid = threadIdx.x;
    int w = tid >> 5, lane = tid & 31;
    int gid = lane >> 2, q = lane & 3;
    int bid = blockIdx.x;
    int nb    = (bid < 124) ? 14 : 13;
    int bbase = (bid < 124) ? bid * 14 : 1736 + (bid - 124) * 13;
    int mcmax = 2 * nb - 1;

    // ---- stage x1 raw (float4) + x0 pairs (float4 passthrough) ----
    {
        const float4* src = (const float4*)(x1g + (size_t)bbase * 1024);
        float4* dst = (float4*)x1r;
        for (int e = tid; e < nb * 256; e += 256) dst[e] = src[e];
        const float4* x0s = (const float4*)(x0g + (size_t)bbase * 1024);
        for (int e = tid; e < nb * 256; e += 256) {
            int bl = e >> 8, r = e & 255;
            int i = r >> 2, dq = r & 3;
            // m = bl*16 + dq*4 .. +3  ->  pairs at x0p[i*112 + bl*8 + dq*2]
            *(float4*)&x0p[i * 112 + bl * 8 + dq * 2] = x0s[e];
        }
    }
    __syncthreads();

    // ---- build B fragments cooperatively: fB[mc*128 + t*32 + ln] ----
    for (int e = tid; e < 3584; e += 256) {
        int mc = e >> 7, t = (e >> 5) & 3, ln = e & 31;
        int r = mc * 8 + (ln >> 2);
        int k0 = t * 16 + (ln & 3) * 2;
        const float* base = x1r + (r >> 4) * 1024 + (r & 15);
        fB[e] = make_uint2(
            pack_half2(base[k0 * 16], base[(k0 + 1) * 16]),
            pack_half2(base[(k0 + 8) * 16], base[(k0 + 9) * 16]));
    }
    __syncthreads();

    // ---- warp roles: Q = w&3 (7 mc chunks), h = w>>2 (32 i's) ----
    int Q = w & 3, h = w >> 2;

    int mcc[7];
    #pragma unroll
    for (int mcl = 0; mcl < 7; ++mcl) {
        int mc = Q * 7 + mcl;
        if (mc > mcmax) mc = mcmax;   // nb=13: duplicate garbage, discarded
        mcc[mcl] = mc;
    }

    // register B fragments via clean LDS.64 (pure fp16 x1, NO x0 fold)
    uint2 Bf[7][4];
    #pragma unroll
    for (int mcl = 0; mcl < 7; ++mcl) {
        const uint2* fp = fB + mcc[mcl] * 128 + lane;
        #pragma unroll
        for (int t = 0; t < 4; ++t)
            Bf[mcl][t] = fp[t * 32];
    }

    float acc[7][4];
    #pragma unroll
    for (int mcl = 0; mcl < 7; ++mcl)
        #pragma unroll
        for (int r = 0; r < 4; ++r) acc[mcl][r] = 0.0f;

    const uint4* wp = g_Wfrag + lane;
    int i0 = h * 32;
    uint4 Wc[4], Wn[4];
    #pragma unroll
    for (int t = 0; t < 4; ++t) Wc[t] = wp[(i0 * 4 + t) * 32];

    // ---- mainloop: per (mcl, il): fresh 4-deep mma chain, fp32 FFMA fold ----
    for (int il = 0; il < 32; ++il) {
        int i = i0 + il;
        if (il < 31) {
            #pragma unroll
            for (int t = 0; t < 4; ++t) Wn[t] = wp[((i + 1) * 4 + t) * 32];
        }
        const float2* x0row = x0p + i * 112 + q;
        #pragma unroll
        for (int mcl = 0; mcl < 7; ++mcl) {
            float2 xv = x0row[mcc[mcl] * 4];   // {x0[m0,i], x0[m0+1,i]}, m0=mc*8+2q
            float c[4] = {0.f, 0.f, 0.f, 0.f};
            mma16816(c, Wc[0], Bf[mcl][0]);
            mma16816(c, Wc[1], Bf[mcl][1]);
            mma16816(c, Wc[2], Bf[mcl][2]);
            mma16816(c, Wc[3], Bf[mcl][3]);
            // c0,c1: l=gid, m = m0,m0+1 ; c2,c3: l=gid+8, same m.
            acc[mcl][0] = fmaf(xv.x, c[0], acc[mcl][0]);
            acc[mcl][1] = fmaf(xv.y, c[1], acc[mcl][1]);
            acc[mcl][2] = fmaf(xv.x, c[2], acc[mcl][2]);
            acc[mcl][3] = fmaf(xv.y, c[3], acc[mcl][3]);
        }
        #pragma unroll
        for (int t = 0; t < 4; ++t) Wc[t] = Wn[t];
    }

    __syncthreads();   // all x0p/x1r/fB reads done; wb overlay safe

    // ---- partial writeback: wb[(w*7+mcl)*136 + l*8 + m_in_chunk] ----
    #pragma unroll
    for (int mcl = 0; mcl < 7; ++mcl) {
        float* bptr = wb + (w * 7 + mcl) * 136;
        *(float2*)&bptr[gid * 8 + 2 * q]       = make_float2(acc[mcl][0], acc[mcl][1]);
        *(float2*)&bptr[(gid + 8) * 8 + 2 * q] = make_float2(acc[mcl][2], acc[mcl][3]);
    }
    __syncthreads();

    // ---- final reduce: 2 i-halves; coalesced store ----
    for (int o = tid; o < nb * 256; o += 256) {
        int bl = o >> 8, l = (o >> 4) & 15, d = o & 15;
        int m = bl * 16 + d;
        int mc = m >> 3;
        int Q2 = (mc * 9363) >> 16;    // mc / 7 for mc < 28
        int mcl = mc - Q2 * 7;
        int e = mcl * 136 + l * 8 + (m & 7);
        float s = wb[(Q2 * 7) * 136 + e] + wb[((4 + Q2) * 7) * 136 + e];
        outg[(size_t)(bbase + bl) * 256 + l * 16 + d] = s;
    }
}

// ------------------------------------------------------------------ launch --
extern "C" void kernel_launch(void* const* d_in, const int* in_sizes, int n_in,
                              void* d_out, int out_size) {
    const float* x0 = (const float*)d_in[0];
    const float* x1 = (const float*)d_in[1];
    const float* filters = (const float*)d_in[2];
    float* out = (float*)d_out;

    cudaFuncSetAttribute(fm_main_kernel,
                         cudaFuncAttributeMaxDynamicSharedMemorySize, SMEM_TOTAL);

    prep_w_kernel<<<32, 256>>>(filters);
    fm_main_kernel<<<148, 256, SMEM_TOTAL>>>(x0, x1, out);
}

// round 17
// speedup vs baseline: 2.1849x; 1.0014x over previous
#include <cuda_runtime.h>
#include <cuda_fp16.h>
#include <cstdint>

// ============================================================================
// out[b,l,d] = sum_{i,j} x0[b,i,d]*x1[b,j,d]*filters[i*64+j, l]
// B=2048, F1=F2=64, D=16, L=16.
//
// R17: R16 (wave-balanced, output-path fold, 22.5us) at 4 warps/SMSP.
// ncu R16: tensor busy 29%, issue 18% -> mma issue-stall-bound at 2 warps/SMSP
// (pipe occupied only ~6.5cyc/mma but issued every ~22.5). block=512, warp =
// (Q = w&3 -> 7 mc, h = w>>2 -> 16 i); same 1792 mma/SMSP, no extra padding.
// Wn prefetch dropped to fit 128 regs @ 512 thr (W is L1-resident; 4 warps
// cover the LDG latency). Reduce sums 4 i-quarters.
// ============================================================================

// Pre-arranged W fragment image: [i(64)][kstep(4)][lane(32)] x 16B.
__device__ __align__(16) uint4 g_Wfrag[64 * 4 * 32];

__device__ __forceinline__ uint32_t pack_half2(float a, float b) {
    __half2 h = __floats2half2_rn(a, b);   // .x (low 16b) = a, .y = b
    return *(uint32_t*)&h;
}
__device__ __forceinline__ void mma16816(float c[4], const uint4& a, const uint2& b) {
    asm volatile(
        "mma.sync.aligned.m16n8k16.row.col.f32.f16.f16.f32 "
        "{%0,%1,%2,%3}, {%4,%5,%6,%7}, {%8,%9}, {%0,%1,%2,%3};\n"
        : "+f"(c[0]), "+f"(c[1]), "+f"(c[2]), "+f"(c[3])
        : "r"(a.x), "r"(a.y), "r"(a.z), "r"(a.w), "r"(b.x), "r"(b.y));
}

// ---------------------------------------------------------- prep kernel -----
// A-fragment mapping (m16k16, row-major), lane = 4*gid + q:
//   reg0 = {A[gid][2q],   A[gid][2q+1]}    reg1 = {A[gid+8][2q],   A[gid+8][2q+1]}
//   reg2 = {A[gid][2q+8], A[gid][2q+9]}    reg3 = {A[gid+8][2q+8], A[gid+8][2q+9]}
__global__ void prep_w_kernel(const float* __restrict__ filters) {
    int idx  = blockIdx.x * 256 + threadIdx.x;    // 8192 total
    int i    = (idx >> 7) & 63;
    int t    = (idx >> 5) & 3;
    int lane = idx & 31;
    int gid = lane >> 2, q = lane & 3;
    int k0 = t * 16 + q * 2;
    int l0 = gid, l1 = gid + 8;

    float e[8];
    int ls[8] = {l0, l0, l1, l1, l0, l0, l1, l1};
    int ks[8] = {k0, k0 + 1, k0, k0 + 1, k0 + 8, k0 + 9, k0 + 8, k0 + 9};
    #pragma unroll
    for (int j = 0; j < 8; ++j)
        e[j] = filters[(i * 64 + ks[j]) * 16 + ls[j]];

    g_Wfrag[idx] = make_uint4(pack_half2(e[0], e[1]), pack_half2(e[2], e[3]),
                              pack_half2(e[4], e[5]), pack_half2(e[6], e[7]));
}

// ------------------------------------------------------------ main kernel ---
// SMEM: x0p 64*112 float2 (57344) | x1r 14*1024 f32 (57344) | fB 3584 uint2
//   (28672) -> 143360.
// Overlay after mainloop: wb = 112 bufs * 136 f (60928 B) spans x0p+x1r
//   (both dead after mainloop); fB untouched above it.
static constexpr int SM_X0P = 0;
static constexpr int SM_X1R = 57344;
static constexpr int SM_FB  = 114688;
static constexpr int SM_WB  = SM_X0P;
static constexpr int SMEM_TOTAL = 143360;

__global__ __launch_bounds__(512, 1) void fm_main_kernel(
    const float* __restrict__ x0g,
    const float* __restrict__ x1g,
    float* __restrict__ outg)
{
    extern __shared__ __align__(16) unsigned char smem[];
    float2*   x0p = (float2*)(smem + SM_X0P);   // [i][m/2] fp32 pairs
    float*    x1r = (float*)(smem + SM_X1R);
    uint2*    fB  = (uint2*)(smem + SM_FB);
    float*    wb  = (float*)(smem + SM_WB);

    int tid = threadIdx.x;
    int w = tid >> 5, lane = tid & 31;
    int gid = lane >> 2, q = lane & 3;
    int bid = blockIdx.x;
    int nb    = (bid < 124) ? 14 : 13;
    int bbase = (bid < 124) ? bid * 14 : 1736 + (bid - 124) * 13;
    int mcmax = 2 * nb - 1;

    // ---- stage x1 raw (float4) + x0 pairs (float4 passthrough) ----
    {
        const float4* src = (const float4*)(x1g + (size_t)bbase * 1024);
        float4* dst = (float4*)x1r;
        for (int e = tid; e < nb * 256; e += 512) dst[e] = src[e];
        const float4* x0s = (const float4*)(x0g + (size_t)bbase * 1024);
        for (int e = tid; e < nb * 256; e += 512) {
            int bl = e >> 8, r = e & 255;
            int i = r >> 2, dq = r & 3;
            *(float4*)&x0p[i * 112 + bl * 8 + dq * 2] = x0s[e];
        }
    }
    __syncthreads();

    // ---- build B fragments cooperatively: fB[mc*128 + t*32 + ln] ----
    for (int e = tid; e < 3584; e += 512) {
        int mc = e >> 7, t = (e >> 5) & 3, ln = e & 31;
        int r = mc * 8 + (ln >> 2);
        int k0 = t * 16 + (ln & 3) * 2;
        const float* base = x1r + (r >> 4) * 1024 + (r & 15);
        fB[e] = make_uint2(
            pack_half2(base[k0 * 16], base[(k0 + 1) * 16]),
            pack_half2(base[(k0 + 8) * 16], base[(k0 + 9) * 16]));
    }
    __syncthreads();

    // ---- warp roles: Q = w&3 (7 mc chunks), h = w>>2 (16 i's) ----
    int Q = w & 3, h = w >> 2;

    int mcc[7];
    #pragma unroll
    for (int mcl = 0; mcl < 7; ++mcl) {
        int mc = Q * 7 + mcl;
        if (mc > mcmax) mc = mcmax;   // nb=13: duplicate garbage, discarded
        mcc[mcl] = mc;
    }

    // register B fragments via clean LDS.64 (pure fp16 x1, NO x0 fold)
    uint2 Bf[7][4];
    #pragma unroll
    for (int mcl = 0; mcl < 7; ++mcl) {
        const uint2* fp = fB + mcc[mcl] * 128 + lane;
        #pragma unroll
        for (int t = 0; t < 4; ++t)
            Bf[mcl][t] = fp[t * 32];
    }

    float acc[7][4];
    #pragma unroll
    for (int mcl = 0; mcl < 7; ++mcl)
        #pragma unroll
        for (int r = 0; r < 4; ++r) acc[mcl][r] = 0.0f;

    const uint4* wp = g_Wfrag + lane;
    int i0 = h * 16;

    // ---- mainloop: 16 i's; per (mcl, il) fresh 4-deep mma chain + fp32 fold
    for (int il = 0; il < 16; ++il) {
        int i = i0 + il;
        uint4 Wc[4];
        #pragma unroll
        for (int t = 0; t < 4; ++t) Wc[t] = wp[(i * 4 + t) * 32];
        const float2* x0row = x0p + i * 112 + q;
        #pragma unroll
        for (int mcl = 0; mcl < 7; ++mcl) {
            float2 xv = x0row[mcc[mcl] * 4];   // {x0[m0,i], x0[m0+1,i]}
            float c[4] = {0.f, 0.f, 0.f, 0.f};
            mma16816(c, Wc[0], Bf[mcl][0]);
            mma16816(c, Wc[1], Bf[mcl][1]);
            mma16816(c, Wc[2], Bf[mcl][2]);
            mma16816(c, Wc[3], Bf[mcl][3]);
            // c0,c1: l=gid, m = m0,m0+1 ; c2,c3: l=gid+8, same m.
            acc[mcl][0] = fmaf(xv.x, c[0], acc[mcl][0]);
            acc[mcl][1] = fmaf(xv.y, c[1], acc[mcl][1]);
            acc[mcl][2] = fmaf(xv.x, c[2], acc[mcl][2]);
            acc[mcl][3] = fmaf(xv.y, c[3], acc[mcl][3]);
        }
    }

    __syncthreads();   // all x0p/x1r/fB reads done; wb overlay safe

    // ---- partial writeback: wb[(w*7+mcl)*136 + l*8 + m_in_chunk] ----
    #pragma unroll
    for (int mcl = 0; mcl < 7; ++mcl) {
        float* bptr = wb + (w * 7 + mcl) * 136;
        *(float2*)&bptr[gid * 8 + 2 * q]       = make_float2(acc[mcl][0], acc[mcl][1]);
        *(float2*)&bptr[(gid + 8) * 8 + 2 * q] = make_float2(acc[mcl][2], acc[mcl][3]);
    }
    __syncthreads();

    // ---- final reduce: 4 i-quarters; coalesced store ----
    for (int o = tid; o < nb * 256; o += 512) {
        int bl = o >> 8, l = (o >> 4) & 15, d = o & 15;
        int m = bl * 16 + d;
        int mc = m >> 3;
        int Q2 = (mc * 9363) >> 16;    // mc / 7 for mc < 28
        int mcl = mc - Q2 * 7;
        int e = (Q2 * 7 + mcl) * 136 + l * 8 + (m & 7);
        float s = wb[e] + wb[e + 28 * 136] + wb[e + 56 * 136] + wb[e + 84 * 136];
        outg[(size_t)(bbase + bl) * 256 + l * 16 + d] = s;
    }
}

// ------------------------------------------------------------------ launch --
extern "C" void kernel_launch(void* const* d_in, const int* in_sizes, int n_in,
                              void* d_out, int out_size) {
    const float* x0 = (const float*)d_in[0];
    const float* x1 = (const float*)d_in[1];
    const float* filters = (const float*)d_in[2];
    float* out = (float*)d_out;

    cudaFuncSetAttribute(fm_main_kernel,
                         cudaFuncAttributeMaxDynamicSharedMemorySize, SMEM_TOTAL);

    prep_w_kernel<<<32, 256>>>(filters);
    fm_main_kernel<<<148, 512, SMEM_TOTAL>>>(x0, x1, out);
}